// round 12
// baseline (speedup 1.0000x reference)
#include <cuda_runtime.h>
#include <cuda_bf16.h>
#include <cstdint>

#define PB 2
#define PL 2048
#define PD 1024
#define PH 16
#define PDh 64
#define PM (PB * PL)

// Pre-split bf16 hi/lo operands (device globals; no runtime alloc)
__device__ __nv_bfloat16 g_x_hi[PM * PD],  g_x_lo[PM * PD];
__device__ __nv_bfloat16 g_wq_hi[PD * PD], g_wq_lo[PD * PD];
__device__ __nv_bfloat16 g_wk_hi[PD * PD], g_wk_lo[PD * PD];
__device__ __nv_bfloat16 g_wv_hi[PD * PD], g_wv_lo[PD * PD];
__device__ __nv_bfloat16 g_wo_hi[PD * PD], g_wo_lo[PD * PD];
__device__ __nv_bfloat16 g_q_hi[PM * PD],  g_q_lo[PM * PD];
__device__ __nv_bfloat16 g_k_hi[PM * PD],  g_k_lo[PM * PD];
__device__ __nv_bfloat16 g_v_hi[PM * PD],  g_v_lo[PM * PD];
__device__ __nv_bfloat16 g_o_hi[PM * PD],  g_o_lo[PM * PD];

__device__ __forceinline__ uint32_t smem_u32(const void* p) {
    return (uint32_t)__cvta_generic_to_shared(p);
}
__device__ __forceinline__ void cp_async16(uint32_t s, const void* g) {
    asm volatile("cp.async.cg.shared.global [%0], [%1], 16;" :: "r"(s), "l"(g));
}
__device__ __forceinline__ void cp_commit() {
    asm volatile("cp.async.commit_group;");
}
template<int N>
__device__ __forceinline__ void cp_wait() {
    asm volatile("cp.async.wait_group %0;" :: "n"(N));
}
__device__ __forceinline__ void ldsm_x4(uint32_t& r0, uint32_t& r1, uint32_t& r2, uint32_t& r3, uint32_t a) {
    asm volatile("ldmatrix.sync.aligned.m8n8.x4.shared.b16 {%0,%1,%2,%3}, [%4];"
                 : "=r"(r0), "=r"(r1), "=r"(r2), "=r"(r3) : "r"(a));
}
__device__ __forceinline__ void ldsm_x4t(uint32_t& r0, uint32_t& r1, uint32_t& r2, uint32_t& r3, uint32_t a) {
    asm volatile("ldmatrix.sync.aligned.m8n8.x4.trans.shared.b16 {%0,%1,%2,%3}, [%4];"
                 : "=r"(r0), "=r"(r1), "=r"(r2), "=r"(r3) : "r"(a));
}
__device__ __forceinline__ void ldsm_x2t(uint32_t& r0, uint32_t& r1, uint32_t a) {
    asm volatile("ldmatrix.sync.aligned.m8n8.x2.trans.shared.b16 {%0,%1}, [%2];"
                 : "=r"(r0), "=r"(r1) : "r"(a));
}
__device__ __forceinline__ void mma_bf16(float* d, uint32_t a0, uint32_t a1, uint32_t a2, uint32_t a3,
                                         uint32_t b0, uint32_t b1) {
    asm volatile("mma.sync.aligned.m16n8k16.row.col.f32.bf16.bf16.f32 "
                 "{%0,%1,%2,%3}, {%4,%5,%6,%7}, {%8,%9}, {%0,%1,%2,%3};"
                 : "+f"(d[0]), "+f"(d[1]), "+f"(d[2]), "+f"(d[3])
                 : "r"(a0), "r"(a1), "r"(a2), "r"(a3), "r"(b0), "r"(b1));
}
__device__ __forceinline__ void split_pair(float x, float y, uint32_t& hi, uint32_t& lo) {
    __nv_bfloat162 h2, l2;
    h2.x = __float2bfloat16(x);
    h2.y = __float2bfloat16(y);
    l2.x = __float2bfloat16(x - __bfloat162float(h2.x));
    l2.y = __float2bfloat16(y - __bfloat162float(h2.y));
    hi = *reinterpret_cast<uint32_t*>(&h2);
    lo = *reinterpret_cast<uint32_t*>(&l2);
}

// ---------------------------------------------------------------------------
// fp32 -> bf16 hi/lo split of the 5 inputs
// ---------------------------------------------------------------------------
__global__ __launch_bounds__(256) void split_all_kernel(
    const float* __restrict__ x,  const float* __restrict__ wq,
    const float* __restrict__ wk, const float* __restrict__ wv,
    const float* __restrict__ wo) {
    const int which = blockIdx.y;
    const float* src; __nv_bfloat16 *hi, *lo; int n2;
    if      (which == 0) { src = x;  hi = g_x_hi;  lo = g_x_lo;  n2 = PM * PD / 2; }
    else if (which == 1) { src = wq; hi = g_wq_hi; lo = g_wq_lo; n2 = PD * PD / 2; }
    else if (which == 2) { src = wk; hi = g_wk_hi; lo = g_wk_lo; n2 = PD * PD / 2; }
    else if (which == 3) { src = wv; hi = g_wv_hi; lo = g_wv_lo; n2 = PD * PD / 2; }
    else                 { src = wo; hi = g_wo_hi; lo = g_wo_lo; n2 = PD * PD / 2; }
    for (int i = blockIdx.x * 256 + threadIdx.x; i < n2; i += gridDim.x * 256) {
        float2 v = ((const float2*)src)[i];
        uint32_t h, l;
        split_pair(v.x, v.y, h, l);
        ((uint32_t*)hi)[i] = h;
        ((uint32_t*)lo)[i] = l;
    }
}

// ---------------------------------------------------------------------------
// bf16x3 MMA GEMM, 2-stage cp.async pipeline.
// C[4096x1024] = A[4096x1024] * B[1024x1024] (row-major).
// 128x128 tile, K-tile 32, 8 warps of 64x32. MODE 0: hi/lo out. MODE 1: fp32.
// ---------------------------------------------------------------------------
#define SA 40                      // A smem row stride (bf16): 32 + 8 pad (80B)
#define SB 136                     // B smem row stride (bf16): 128 + 8 pad (272B)
#define GA_STG (128 * SA * 2)      // A stage bytes (10240)
#define GB_STG (32 * SB * 2)       // B stage bytes (8704)
#define GEMM_SMEM (2 * (2 * GA_STG + 2 * GB_STG))   // 75776 B

__device__ __forceinline__ void gemm_load_stage(
    int tid, int kt,
    const uint32_t* gAh, const uint32_t* gAl,
    const uint32_t* gBh, const uint32_t* gBl,
    uint32_t sAh, uint32_t sAl, uint32_t sBh, uint32_t sBl) {
    // A: 128 rows x 4 chunks(16B) x {hi,lo} = 1024 chunks
#pragma unroll
    for (int i = 0; i < 4; i++) {
        int w = tid + i * 256;
        int half = w >> 9, rem = w & 511;
        int m = rem >> 2, c = rem & 3;
        const uint32_t* g = (half ? gAl : gAh) + (size_t)m * 512 + (kt >> 1) + c * 4;
        cp_async16((half ? sAl : sAh) + m * (SA * 2) + c * 16, g);
    }
    // B: 32 rows x 16 chunks(16B) x {hi,lo} = 1024 chunks
#pragma unroll
    for (int i = 0; i < 4; i++) {
        int w = tid + i * 256;
        int half = w >> 9, rem = w & 511;
        int k = rem >> 4, c = rem & 15;
        const uint32_t* g = (half ? gBl : gBh) + (size_t)(kt + k) * 512 + c * 4;
        cp_async16((half ? sBl : sBh) + k * (SB * 2) + c * 16, g);
    }
}

template<int MODE>
__device__ __forceinline__ void gemm_1024(
    const __nv_bfloat16* __restrict__ Ah, const __nv_bfloat16* __restrict__ Al,
    const __nv_bfloat16* __restrict__ Bh, const __nv_bfloat16* __restrict__ Bl,
    __nv_bfloat16* __restrict__ Ch, __nv_bfloat16* __restrict__ Cl,
    float* __restrict__ Cf) {

    extern __shared__ __align__(16) char dynsm[];
    // layout: sAh[2 stages] | sAl[2] | sBh[2] | sBl[2]
    const uint32_t base   = smem_u32(dynsm);
    const uint32_t bAh0 = base;
    const uint32_t bAl0 = bAh0 + 2 * GA_STG;
    const uint32_t bBh0 = bAl0 + 2 * GA_STG;
    const uint32_t bBl0 = bBh0 + 2 * GB_STG;

    const int tid = threadIdx.x;
    const int lane = tid & 31, warp = tid >> 5;
    const int wm = (warp >> 2) * 64;
    const int wn = (warp & 3) * 32;
    const int rowBase = blockIdx.y * 128;
    const int colBase = blockIdx.x * 128;

    float acc[4][4][4];
#pragma unroll
    for (int mi = 0; mi < 4; mi++)
#pragma unroll
        for (int ni = 0; ni < 4; ni++)
#pragma unroll
            for (int j = 0; j < 4; j++) acc[mi][ni][j] = 0.f;

    const uint32_t* gAh = (const uint32_t*)Ah + (size_t)rowBase * 512;
    const uint32_t* gAl = (const uint32_t*)Al + (size_t)rowBase * 512;
    const uint32_t* gBh = (const uint32_t*)Bh + (colBase >> 1);
    const uint32_t* gBl = (const uint32_t*)Bl + (colBase >> 1);

    const int aRow  = (lane & 7) + ((lane >> 3) & 1) * 8;
    const int aCol8 = ((lane >> 4) & 1) * 8;
    const int bRow  = (lane & 7) + ((lane >> 3) & 1) * 8;

    // Prologue: stage 0
    gemm_load_stage(tid, 0, gAh, gAl, gBh, gBl, bAh0, bAl0, bBh0, bBl0);
    cp_commit();

    for (int kt = 0; kt < 1024; kt += 32) {
        const int s = (kt >> 5) & 1;
        if (kt + 32 < 1024) {
            const int sn = s ^ 1;
            gemm_load_stage(tid, kt + 32, gAh, gAl, gBh, gBl,
                            bAh0 + sn * GA_STG, bAl0 + sn * GA_STG,
                            bBh0 + sn * GB_STG, bBl0 + sn * GB_STG);
        }
        cp_commit();
        cp_wait<1>();
        __syncthreads();

        const uint32_t baseAh = bAh0 + s * GA_STG;
        const uint32_t baseAl = bAl0 + s * GA_STG;
        const uint32_t baseBh = bBh0 + s * GB_STG;
        const uint32_t baseBl = bBl0 + s * GB_STG;

#pragma unroll
        for (int ks = 0; ks < 2; ks++) {
            uint32_t bh[4][2], bl[4][2];
#pragma unroll
            for (int ni = 0; ni < 4; ni++) {
                uint32_t off = (uint32_t)(((ks * 16 + bRow) * SB + wn + ni * 8) * 2);
                ldsm_x2t(bh[ni][0], bh[ni][1], baseBh + off);
                ldsm_x2t(bl[ni][0], bl[ni][1], baseBl + off);
            }
#pragma unroll
            for (int mi = 0; mi < 4; mi++) {
                uint32_t off = (uint32_t)(((wm + mi * 16 + aRow) * SA + ks * 16 + aCol8) * 2);
                uint32_t a0, a1, a2, a3, l0, l1, l2, l3;
                ldsm_x4(a0, a1, a2, a3, baseAh + off);
                ldsm_x4(l0, l1, l2, l3, baseAl + off);
#pragma unroll
                for (int ni = 0; ni < 4; ni++) {
                    mma_bf16(acc[mi][ni], a0, a1, a2, a3, bh[ni][0], bh[ni][1]);
                    mma_bf16(acc[mi][ni], l0, l1, l2, l3, bh[ni][0], bh[ni][1]);
                    mma_bf16(acc[mi][ni], a0, a1, a2, a3, bl[ni][0], bl[ni][1]);
                }
            }
        }
        __syncthreads();
    }

    const int g = lane >> 2, t0 = lane & 3;
#pragma unroll
    for (int mi = 0; mi < 4; mi++) {
        int r0 = rowBase + wm + mi * 16 + g;
#pragma unroll
        for (int ni = 0; ni < 4; ni++) {
            int col = colBase + wn + ni * 8 + 2 * t0;
            float c0 = acc[mi][ni][0], c1 = acc[mi][ni][1];
            float c2 = acc[mi][ni][2], c3 = acc[mi][ni][3];
            if (MODE == 1) {
                ((float2*)Cf)[((size_t)r0 * 1024 + col) >> 1]       = make_float2(c0, c1);
                ((float2*)Cf)[((size_t)(r0 + 8) * 1024 + col) >> 1] = make_float2(c2, c3);
            } else {
                uint32_t h, l;
                split_pair(c0, c1, h, l);
                ((uint32_t*)Ch)[(size_t)r0 * 512 + (col >> 1)] = h;
                ((uint32_t*)Cl)[(size_t)r0 * 512 + (col >> 1)] = l;
                split_pair(c2, c3, h, l);
                ((uint32_t*)Ch)[(size_t)(r0 + 8) * 512 + (col >> 1)] = h;
                ((uint32_t*)Cl)[(size_t)(r0 + 8) * 512 + (col >> 1)] = l;
            }
        }
    }
}

__global__ __launch_bounds__(256, 2) void qkv_mma_kernel() {
    const int z = blockIdx.z;
    if (z == 0)      gemm_1024<0>(g_x_hi, g_x_lo, g_wq_hi, g_wq_lo, g_q_hi, g_q_lo, nullptr);
    else if (z == 1) gemm_1024<0>(g_x_hi, g_x_lo, g_wk_hi, g_wk_lo, g_k_hi, g_k_lo, nullptr);
    else             gemm_1024<0>(g_x_hi, g_x_lo, g_wv_hi, g_wv_lo, g_v_hi, g_v_lo, nullptr);
}
__global__ __launch_bounds__(256, 2) void out_mma_kernel(float* __restrict__ out) {
    gemm_1024<1>(g_o_hi, g_o_lo, g_wo_hi, g_wo_lo, nullptr, nullptr, out);
}

// ---------------------------------------------------------------------------
// Tensor-core causal flash attention, 2-stage cp.async pipeline on K/V tiles.
// 64 q-rows/block, 4 warps x 16 rows.
// ---------------------------------------------------------------------------
#define AKS 72
#define AT_STG (64 * AKS * 2)                 // per array per stage: 9216 B
#define ATTN_SMEM (4 * 2 * AT_STG)            // 73728 B

__device__ __forceinline__ void attn_load_stage(
    int tid, int jb,
    const uint32_t* gkh, const uint32_t* gkl,
    const uint32_t* gvh, const uint32_t* gvl,
    uint32_t bKh, uint32_t bKl, uint32_t bVh, uint32_t bVl) {
    // 4 arrays x 64 rows x 8 chunks(16B) = 2048 chunks / 128 threads
#pragma unroll
    for (int i = 0; i < 16; i++) {
        int w = tid + i * 128;
        int arr = w >> 9, rem = w & 511;
        int r = rem >> 3, c = rem & 7;
        const uint32_t* g = (arr == 0 ? gkh : arr == 1 ? gkl : arr == 2 ? gvh : gvl)
                            + (size_t)(jb + r) * 512 + c * 4;
        uint32_t s = (arr == 0 ? bKh : arr == 1 ? bKl : arr == 2 ? bVh : bVl)
                     + r * (AKS * 2) + c * 16;
        cp_async16(s, g);
    }
}

__global__ __launch_bounds__(128, 2) void attn_mma_kernel() {
    extern __shared__ __align__(16) char dynsm[];
    const uint32_t bKh0 = smem_u32(dynsm);
    const uint32_t bKl0 = bKh0 + 2 * AT_STG;
    const uint32_t bVh0 = bKl0 + 2 * AT_STG;
    const uint32_t bVl0 = bVh0 + 2 * AT_STG;

    const int tid = threadIdx.x;
    const int lane = tid & 31, warp = tid >> 5;
    const int g = lane >> 2, t0 = lane & 3;
    const int h = blockIdx.y, b = blockIdx.z;
    const int qb = (int)(gridDim.x - 1 - blockIdx.x) * 64;   // heavy blocks first
    const int rowG = b * PL + qb + warp * 16;

    // Preload Q A-fragments (hi/lo), pre-scaled by 1/sqrt(Dh)=0.125 (exact)
    uint32_t qah[4][4], qal[4][4];
    {
        const uint32_t* qh32 = (const uint32_t*)g_q_hi;
        const uint32_t* ql32 = (const uint32_t*)g_q_lo;
        const __nv_bfloat162 sc2 = __float2bfloat162_rn(0.125f);
        size_t r0 = (size_t)(rowG + g) * 512, r1 = (size_t)(rowG + g + 8) * 512;
#pragma unroll
        for (int ks = 0; ks < 4; ks++) {
            int c = h * 32 + ks * 8 + t0;
            uint32_t v[8] = { qh32[r0 + c], qh32[r1 + c], qh32[r0 + c + 4], qh32[r1 + c + 4],
                              ql32[r0 + c], ql32[r1 + c], ql32[r0 + c + 4], ql32[r1 + c + 4] };
#pragma unroll
            for (int j = 0; j < 8; j++) {
                __nv_bfloat162 t = __hmul2(*reinterpret_cast<__nv_bfloat162*>(&v[j]), sc2);
                v[j] = *reinterpret_cast<uint32_t*>(&t);
            }
#pragma unroll
            for (int j = 0; j < 4; j++) { qah[ks][j] = v[j]; qal[ks][j] = v[j + 4]; }
        }
    }

    float oacc[8][4];
#pragma unroll
    for (int dn = 0; dn < 8; dn++)
#pragma unroll
        for (int j = 0; j < 4; j++) oacc[dn][j] = 0.f;
    float m0 = -1e30f, m1 = -1e30f, l0 = 0.f, l1 = 0.f;

    const int nA = lane & 7;
    const int sel8 = ((lane >> 3) & 1) * 8;
    const int sel16 = ((lane >> 4) & 1);
    const int qrow = qb + warp * 16 + g;

    const uint32_t* gkh = (const uint32_t*)g_k_hi + (size_t)(b * PL) * 512 + h * 32;
    const uint32_t* gkl = (const uint32_t*)g_k_lo + (size_t)(b * PL) * 512 + h * 32;
    const uint32_t* gvh = (const uint32_t*)g_v_hi + (size_t)(b * PL) * 512 + h * 32;
    const uint32_t* gvl = (const uint32_t*)g_v_lo + (size_t)(b * PL) * 512 + h * 32;

    const int ntiles = (qb >> 6) + 1;

    // Prologue: tile 0 into stage 0
    attn_load_stage(tid, 0, gkh, gkl, gvh, gvl, bKh0, bKl0, bVh0, bVl0);
    cp_commit();

    for (int t = 0; t < ntiles; t++) {
        const int jb = t * 64;
        const int s = t & 1;
        if (t + 1 < ntiles) {
            const int sn = s ^ 1;
            attn_load_stage(tid, jb + 64, gkh, gkl, gvh, gvl,
                            bKh0 + sn * AT_STG, bKl0 + sn * AT_STG,
                            bVh0 + sn * AT_STG, bVl0 + sn * AT_STG);
        }
        cp_commit();
        cp_wait<1>();
        __syncthreads();

        const uint32_t bKh = bKh0 + s * AT_STG, bKl = bKl0 + s * AT_STG;
        const uint32_t bVh = bVh0 + s * AT_STG, bVl = bVl0 + s * AT_STG;

        // ---- S = Q*K^T (16x64 per warp), 3-pass bf16 ----
        float sS[8][4];
#pragma unroll
        for (int ni = 0; ni < 8; ni++)
#pragma unroll
            for (int j = 0; j < 4; j++) sS[ni][j] = 0.f;

#pragma unroll
        for (int ks = 0; ks < 4; ks++) {
#pragma unroll
            for (int np = 0; np < 4; np++) {
                uint32_t off = (uint32_t)((((np * 2 + sel16) * 8 + nA) * AKS + ks * 16 + sel8) * 2);
                uint32_t kh0, kh1, kh2, kh3, kl0, kl1, kl2, kl3;
                ldsm_x4(kh0, kh1, kh2, kh3, bKh + off);
                ldsm_x4(kl0, kl1, kl2, kl3, bKl + off);
                mma_bf16(sS[np * 2],     qah[ks][0], qah[ks][1], qah[ks][2], qah[ks][3], kh0, kh1);
                mma_bf16(sS[np * 2],     qal[ks][0], qal[ks][1], qal[ks][2], qal[ks][3], kh0, kh1);
                mma_bf16(sS[np * 2],     qah[ks][0], qah[ks][1], qah[ks][2], qah[ks][3], kl0, kl1);
                mma_bf16(sS[np * 2 + 1], qah[ks][0], qah[ks][1], qah[ks][2], qah[ks][3], kh2, kh3);
                mma_bf16(sS[np * 2 + 1], qal[ks][0], qal[ks][1], qal[ks][2], qal[ks][3], kh2, kh3);
                mma_bf16(sS[np * 2 + 1], qah[ks][0], qah[ks][1], qah[ks][2], qah[ks][3], kl2, kl3);
            }
        }

        // Causal mask (diagonal tile only)
        if (jb == qb) {
            int r1 = qrow + 8;
#pragma unroll
            for (int ni = 0; ni < 8; ni++) {
                int k0 = jb + ni * 8 + 2 * t0;
                if (k0     > qrow) sS[ni][0] = -1e30f;
                if (k0 + 1 > qrow) sS[ni][1] = -1e30f;
                if (k0     > r1)   sS[ni][2] = -1e30f;
                if (k0 + 1 > r1)   sS[ni][3] = -1e30f;
            }
        }

        // ---- online softmax ----
        float cm0 = -1e30f, cm1 = -1e30f;
#pragma unroll
        for (int ni = 0; ni < 8; ni++) {
            cm0 = fmaxf(cm0, fmaxf(sS[ni][0], sS[ni][1]));
            cm1 = fmaxf(cm1, fmaxf(sS[ni][2], sS[ni][3]));
        }
        cm0 = fmaxf(cm0, __shfl_xor_sync(0xffffffffu, cm0, 1));
        cm0 = fmaxf(cm0, __shfl_xor_sync(0xffffffffu, cm0, 2));
        cm1 = fmaxf(cm1, __shfl_xor_sync(0xffffffffu, cm1, 1));
        cm1 = fmaxf(cm1, __shfl_xor_sync(0xffffffffu, cm1, 2));
        float nm0 = fmaxf(m0, cm0), nm1 = fmaxf(m1, cm1);
        float corr0 = __expf(m0 - nm0), corr1 = __expf(m1 - nm1);
        m0 = nm0; m1 = nm1;
        l0 *= corr0; l1 *= corr1;
#pragma unroll
        for (int dn = 0; dn < 8; dn++) {
            oacc[dn][0] *= corr0; oacc[dn][1] *= corr0;
            oacc[dn][2] *= corr1; oacc[dn][3] *= corr1;
        }
#pragma unroll
        for (int ni = 0; ni < 8; ni++) {
            sS[ni][0] = __expf(sS[ni][0] - nm0); sS[ni][1] = __expf(sS[ni][1] - nm0);
            sS[ni][2] = __expf(sS[ni][2] - nm1); sS[ni][3] = __expf(sS[ni][3] - nm1);
            l0 += sS[ni][0] + sS[ni][1];
            l1 += sS[ni][2] + sS[ni][3];
        }

        // P -> bf16 hi/lo A-fragments (C-frag layout == A-frag layout)
        uint32_t pah[4][4], pal[4][4];
#pragma unroll
        for (int ks2 = 0; ks2 < 4; ks2++) {
            split_pair(sS[2 * ks2][0],     sS[2 * ks2][1],     pah[ks2][0], pal[ks2][0]);
            split_pair(sS[2 * ks2][2],     sS[2 * ks2][3],     pah[ks2][1], pal[ks2][1]);
            split_pair(sS[2 * ks2 + 1][0], sS[2 * ks2 + 1][1], pah[ks2][2], pal[ks2][2]);
            split_pair(sS[2 * ks2 + 1][2], sS[2 * ks2 + 1][3], pah[ks2][3], pal[ks2][3]);
        }

        // ---- O += P*V, 3-pass bf16 ----
#pragma unroll
        for (int ks2 = 0; ks2 < 4; ks2++) {
#pragma unroll
            for (int dp = 0; dp < 4; dp++) {
                uint32_t off = (uint32_t)(((ks2 * 16 + nA + sel8) * AKS + (dp * 2 + sel16) * 8) * 2);
                uint32_t vh0, vh1, vh2, vh3, vl0, vl1, vl2, vl3;
                ldsm_x4t(vh0, vh1, vh2, vh3, bVh + off);
                ldsm_x4t(vl0, vl1, vl2, vl3, bVl + off);
                mma_bf16(oacc[dp * 2],     pah[ks2][0], pah[ks2][1], pah[ks2][2], pah[ks2][3], vh0, vh1);
                mma_bf16(oacc[dp * 2],     pal[ks2][0], pal[ks2][1], pal[ks2][2], pal[ks2][3], vh0, vh1);
                mma_bf16(oacc[dp * 2],     pah[ks2][0], pah[ks2][1], pah[ks2][2], pah[ks2][3], vl0, vl1);
                mma_bf16(oacc[dp * 2 + 1], pah[ks2][0], pah[ks2][1], pah[ks2][2], pah[ks2][3], vh2, vh3);
                mma_bf16(oacc[dp * 2 + 1], pal[ks2][0], pal[ks2][1], pal[ks2][2], pal[ks2][3], vh2, vh3);
                mma_bf16(oacc[dp * 2 + 1], pah[ks2][0], pah[ks2][1], pah[ks2][2], pah[ks2][3], vl2, vl3);
            }
        }
        __syncthreads();
    }

    // Reduce row sums across quad, normalize, write O as hi/lo
    l0 += __shfl_xor_sync(0xffffffffu, l0, 1);
    l0 += __shfl_xor_sync(0xffffffffu, l0, 2);
    l1 += __shfl_xor_sync(0xffffffffu, l1, 1);
    l1 += __shfl_xor_sync(0xffffffffu, l1, 2);
    float inv0 = 1.f / l0, inv1 = 1.f / l1;

    uint32_t* oh32 = (uint32_t*)g_o_hi;
    uint32_t* ol32 = (uint32_t*)g_o_lo;
    size_t r0 = (size_t)(rowG + g) * 512, r1 = (size_t)(rowG + g + 8) * 512;
#pragma unroll
    for (int dn = 0; dn < 8; dn++) {
        int c = h * 32 + dn * 4 + t0;
        uint32_t hh, ll;
        split_pair(oacc[dn][0] * inv0, oacc[dn][1] * inv0, hh, ll);
        oh32[r0 + c] = hh; ol32[r0 + c] = ll;
        split_pair(oacc[dn][2] * inv1, oacc[dn][3] * inv1, hh, ll);
        oh32[r1 + c] = hh; ol32[r1 + c] = ll;
    }
}

// ---------------------------------------------------------------------------
extern "C" void kernel_launch(void* const* d_in, const int* in_sizes, int n_in,
                              void* d_out, int out_size) {
    const float* x    = (const float*)d_in[0];
    const float* Wq   = (const float*)d_in[1];
    const float* Wk   = (const float*)d_in[2];
    const float* Wv   = (const float*)d_in[3];
    const float* Wout = (const float*)d_in[4];
    float* out = (float*)d_out;

    cudaFuncSetAttribute(qkv_mma_kernel, cudaFuncAttributeMaxDynamicSharedMemorySize, GEMM_SMEM);
    cudaFuncSetAttribute(out_mma_kernel, cudaFuncAttributeMaxDynamicSharedMemorySize, GEMM_SMEM);
    cudaFuncSetAttribute(attn_mma_kernel, cudaFuncAttributeMaxDynamicSharedMemorySize, ATTN_SMEM);

    dim3 splitGrid(128, 5);
    split_all_kernel<<<splitGrid, 256>>>(x, Wq, Wk, Wv, Wout);

    dim3 gemmGrid(8, 32, 3);
    qkv_mma_kernel<<<gemmGrid, 256, GEMM_SMEM>>>();

    dim3 attnGrid(32, PH, PB);
    attn_mma_kernel<<<attnGrid, 128, ATTN_SMEM>>>();

    dim3 outGrid(8, 32, 1);
    out_mma_kernel<<<outGrid, 256, GEMM_SMEM>>>(out);
}

// round 14
// speedup vs baseline: 1.5650x; 1.5650x over previous
#include <cuda_runtime.h>
#include <cuda_bf16.h>
#include <cstdint>

#define PB 2
#define PL 2048
#define PD 1024
#define PH 16
#define PDh 64
#define PM (PB * PL)

// Pre-split bf16 hi/lo operands (device globals; no runtime alloc)
__device__ __nv_bfloat16 g_x_hi[PM * PD],  g_x_lo[PM * PD];
__device__ __nv_bfloat16 g_wq_hi[PD * PD], g_wq_lo[PD * PD];
__device__ __nv_bfloat16 g_wk_hi[PD * PD], g_wk_lo[PD * PD];
__device__ __nv_bfloat16 g_wv_hi[PD * PD], g_wv_lo[PD * PD];
__device__ __nv_bfloat16 g_wo_hi[PD * PD], g_wo_lo[PD * PD];
__device__ __nv_bfloat16 g_q_hi[PM * PD],  g_q_lo[PM * PD];
__device__ __nv_bfloat16 g_k_hi[PM * PD],  g_k_lo[PM * PD];
__device__ __nv_bfloat16 g_v_hi[PM * PD],  g_v_lo[PM * PD];
__device__ __nv_bfloat16 g_o_hi[PM * PD],  g_o_lo[PM * PD];

__device__ __forceinline__ uint32_t smem_u32(const void* p) {
    return (uint32_t)__cvta_generic_to_shared(p);
}
// L1-caching async copy (.ca — NOT .cg; L1 reuse across co-resident CTAs is load-bearing)
__device__ __forceinline__ void cp_async16(uint32_t s, const void* g) {
    asm volatile("cp.async.ca.shared.global [%0], [%1], 16;" :: "r"(s), "l"(g));
}
__device__ __forceinline__ void cp_commit() {
    asm volatile("cp.async.commit_group;");
}
template<int N>
__device__ __forceinline__ void cp_wait() {
    asm volatile("cp.async.wait_group %0;" :: "n"(N));
}
__device__ __forceinline__ void ldsm_x4(uint32_t& r0, uint32_t& r1, uint32_t& r2, uint32_t& r3, uint32_t a) {
    asm volatile("ldmatrix.sync.aligned.m8n8.x4.shared.b16 {%0,%1,%2,%3}, [%4];"
                 : "=r"(r0), "=r"(r1), "=r"(r2), "=r"(r3) : "r"(a));
}
__device__ __forceinline__ void ldsm_x4t(uint32_t& r0, uint32_t& r1, uint32_t& r2, uint32_t& r3, uint32_t a) {
    asm volatile("ldmatrix.sync.aligned.m8n8.x4.trans.shared.b16 {%0,%1,%2,%3}, [%4];"
                 : "=r"(r0), "=r"(r1), "=r"(r2), "=r"(r3) : "r"(a));
}
__device__ __forceinline__ void ldsm_x2t(uint32_t& r0, uint32_t& r1, uint32_t a) {
    asm volatile("ldmatrix.sync.aligned.m8n8.x2.trans.shared.b16 {%0,%1}, [%2];"
                 : "=r"(r0), "=r"(r1) : "r"(a));
}
__device__ __forceinline__ void mma_bf16(float* d, uint32_t a0, uint32_t a1, uint32_t a2, uint32_t a3,
                                         uint32_t b0, uint32_t b1) {
    asm volatile("mma.sync.aligned.m16n8k16.row.col.f32.bf16.bf16.f32 "
                 "{%0,%1,%2,%3}, {%4,%5,%6,%7}, {%8,%9}, {%0,%1,%2,%3};"
                 : "+f"(d[0]), "+f"(d[1]), "+f"(d[2]), "+f"(d[3])
                 : "r"(a0), "r"(a1), "r"(a2), "r"(a3), "r"(b0), "r"(b1));
}
__device__ __forceinline__ void split_pair(float x, float y, uint32_t& hi, uint32_t& lo) {
    __nv_bfloat162 h2, l2;
    h2.x = __float2bfloat16(x);
    h2.y = __float2bfloat16(y);
    l2.x = __float2bfloat16(x - __bfloat162float(h2.x));
    l2.y = __float2bfloat16(y - __bfloat162float(h2.y));
    hi = *reinterpret_cast<uint32_t*>(&h2);
    lo = *reinterpret_cast<uint32_t*>(&l2);
}

// ---------------------------------------------------------------------------
// fp32 -> bf16 hi/lo split of the 5 inputs
// ---------------------------------------------------------------------------
__global__ __launch_bounds__(256) void split_all_kernel(
    const float* __restrict__ x,  const float* __restrict__ wq,
    const float* __restrict__ wk, const float* __restrict__ wv,
    const float* __restrict__ wo) {
    const int which = blockIdx.y;
    const float* src; __nv_bfloat16 *hi, *lo; int n2;
    if      (which == 0) { src = x;  hi = g_x_hi;  lo = g_x_lo;  n2 = PM * PD / 2; }
    else if (which == 1) { src = wq; hi = g_wq_hi; lo = g_wq_lo; n2 = PD * PD / 2; }
    else if (which == 2) { src = wk; hi = g_wk_hi; lo = g_wk_lo; n2 = PD * PD / 2; }
    else if (which == 3) { src = wv; hi = g_wv_hi; lo = g_wv_lo; n2 = PD * PD / 2; }
    else                 { src = wo; hi = g_wo_hi; lo = g_wo_lo; n2 = PD * PD / 2; }
    for (int i = blockIdx.x * 256 + threadIdx.x; i < n2; i += gridDim.x * 256) {
        float2 v = ((const float2*)src)[i];
        uint32_t h, l;
        split_pair(v.x, v.y, h, l);
        ((uint32_t*)hi)[i] = h;
        ((uint32_t*)lo)[i] = l;
    }
}

// ---------------------------------------------------------------------------
// bf16x3 MMA GEMM, 2-stage cp.async(.ca) pipeline.
// C[4096x1024] = A[4096x1024] * B[1024x1024] (row-major).
// 128x128 tile, K-tile 32, 8 warps of 64x32. MODE 0: hi/lo out. MODE 1: fp32.
// ---------------------------------------------------------------------------
#define SA 40                      // A smem row stride (bf16): 32 + 8 pad (80B)
#define SB 136                     // B smem row stride (bf16): 128 + 8 pad (272B)
#define GA_STG (128 * SA * 2)      // A stage bytes (10240)
#define GB_STG (32 * SB * 2)       // B stage bytes (8704)
#define GEMM_SMEM (2 * (2 * GA_STG + 2 * GB_STG))   // 75776 B

__device__ __forceinline__ void gemm_load_stage(
    int tid, int kt,
    const uint32_t* gAh, const uint32_t* gAl,
    const uint32_t* gBh, const uint32_t* gBl,
    uint32_t sAh, uint32_t sAl, uint32_t sBh, uint32_t sBl) {
    // A: 128 rows x 4 chunks(16B) x {hi,lo} = 1024 chunks
#pragma unroll
    for (int i = 0; i < 4; i++) {
        int w = tid + i * 256;
        int half = w >> 9, rem = w & 511;
        int m = rem >> 2, c = rem & 3;
        const uint32_t* g = (half ? gAl : gAh) + (size_t)m * 512 + (kt >> 1) + c * 4;
        cp_async16((half ? sAl : sAh) + m * (SA * 2) + c * 16, g);
    }
    // B: 32 rows x 16 chunks(16B) x {hi,lo} = 1024 chunks
#pragma unroll
    for (int i = 0; i < 4; i++) {
        int w = tid + i * 256;
        int half = w >> 9, rem = w & 511;
        int k = rem >> 4, c = rem & 15;
        const uint32_t* g = (half ? gBl : gBh) + (size_t)(kt + k) * 512 + c * 4;
        cp_async16((half ? sBl : sBh) + k * (SB * 2) + c * 16, g);
    }
}

template<int MODE>
__device__ __forceinline__ void gemm_1024(
    const __nv_bfloat16* __restrict__ Ah, const __nv_bfloat16* __restrict__ Al,
    const __nv_bfloat16* __restrict__ Bh, const __nv_bfloat16* __restrict__ Bl,
    __nv_bfloat16* __restrict__ Ch, __nv_bfloat16* __restrict__ Cl,
    float* __restrict__ Cf) {

    extern __shared__ __align__(16) char dynsm[];
    const uint32_t base = smem_u32(dynsm);
    const uint32_t bAh0 = base;
    const uint32_t bAl0 = bAh0 + 2 * GA_STG;
    const uint32_t bBh0 = bAl0 + 2 * GA_STG;
    const uint32_t bBl0 = bBh0 + 2 * GB_STG;

    const int tid = threadIdx.x;
    const int lane = tid & 31, warp = tid >> 5;
    const int wm = (warp >> 2) * 64;
    const int wn = (warp & 3) * 32;
    const int rowBase = blockIdx.y * 128;
    const int colBase = blockIdx.x * 128;

    float acc[4][4][4];
#pragma unroll
    for (int mi = 0; mi < 4; mi++)
#pragma unroll
        for (int ni = 0; ni < 4; ni++)
#pragma unroll
            for (int j = 0; j < 4; j++) acc[mi][ni][j] = 0.f;

    const uint32_t* gAh = (const uint32_t*)Ah + (size_t)rowBase * 512;
    const uint32_t* gAl = (const uint32_t*)Al + (size_t)rowBase * 512;
    const uint32_t* gBh = (const uint32_t*)Bh + (colBase >> 1);
    const uint32_t* gBl = (const uint32_t*)Bl + (colBase >> 1);

    const int aRow  = (lane & 7) + ((lane >> 3) & 1) * 8;
    const int aCol8 = ((lane >> 4) & 1) * 8;
    const int bRow  = (lane & 7) + ((lane >> 3) & 1) * 8;

    gemm_load_stage(tid, 0, gAh, gAl, gBh, gBl, bAh0, bAl0, bBh0, bBl0);
    cp_commit();

    for (int kt = 0; kt < 1024; kt += 32) {
        const int s = (kt >> 5) & 1;
        if (kt + 32 < 1024) {
            const int sn = s ^ 1;
            gemm_load_stage(tid, kt + 32, gAh, gAl, gBh, gBl,
                            bAh0 + sn * GA_STG, bAl0 + sn * GA_STG,
                            bBh0 + sn * GB_STG, bBl0 + sn * GB_STG);
        }
        cp_commit();
        cp_wait<1>();
        __syncthreads();

        const uint32_t baseAh = bAh0 + s * GA_STG;
        const uint32_t baseAl = bAl0 + s * GA_STG;
        const uint32_t baseBh = bBh0 + s * GB_STG;
        const uint32_t baseBl = bBl0 + s * GB_STG;

#pragma unroll
        for (int ks = 0; ks < 2; ks++) {
            uint32_t bh[4][2], bl[4][2];
#pragma unroll
            for (int ni = 0; ni < 4; ni++) {
                uint32_t off = (uint32_t)(((ks * 16 + bRow) * SB + wn + ni * 8) * 2);
                ldsm_x2t(bh[ni][0], bh[ni][1], baseBh + off);
                ldsm_x2t(bl[ni][0], bl[ni][1], baseBl + off);
            }
#pragma unroll
            for (int mi = 0; mi < 4; mi++) {
                uint32_t off = (uint32_t)(((wm + mi * 16 + aRow) * SA + ks * 16 + aCol8) * 2);
                uint32_t a0, a1, a2, a3, l0, l1, l2, l3;
                ldsm_x4(a0, a1, a2, a3, baseAh + off);
                ldsm_x4(l0, l1, l2, l3, baseAl + off);
#pragma unroll
                for (int ni = 0; ni < 4; ni++) {
                    mma_bf16(acc[mi][ni], a0, a1, a2, a3, bh[ni][0], bh[ni][1]);
                    mma_bf16(acc[mi][ni], l0, l1, l2, l3, bh[ni][0], bh[ni][1]);
                    mma_bf16(acc[mi][ni], a0, a1, a2, a3, bl[ni][0], bl[ni][1]);
                }
            }
        }
        __syncthreads();
    }

    const int g = lane >> 2, t0 = lane & 3;
#pragma unroll
    for (int mi = 0; mi < 4; mi++) {
        int r0 = rowBase + wm + mi * 16 + g;
#pragma unroll
        for (int ni = 0; ni < 4; ni++) {
            int col = colBase + wn + ni * 8 + 2 * t0;
            float c0 = acc[mi][ni][0], c1 = acc[mi][ni][1];
            float c2 = acc[mi][ni][2], c3 = acc[mi][ni][3];
            if (MODE == 1) {
                ((float2*)Cf)[((size_t)r0 * 1024 + col) >> 1]       = make_float2(c0, c1);
                ((float2*)Cf)[((size_t)(r0 + 8) * 1024 + col) >> 1] = make_float2(c2, c3);
            } else {
                uint32_t h, l;
                split_pair(c0, c1, h, l);
                ((uint32_t*)Ch)[(size_t)r0 * 512 + (col >> 1)] = h;
                ((uint32_t*)Cl)[(size_t)r0 * 512 + (col >> 1)] = l;
                split_pair(c2, c3, h, l);
                ((uint32_t*)Ch)[(size_t)(r0 + 8) * 512 + (col >> 1)] = h;
                ((uint32_t*)Cl)[(size_t)(r0 + 8) * 512 + (col >> 1)] = l;
            }
        }
    }
}

__global__ __launch_bounds__(256, 2) void qkv_mma_kernel() {
    const int z = blockIdx.z;
    if (z == 0)      gemm_1024<0>(g_x_hi, g_x_lo, g_wq_hi, g_wq_lo, g_q_hi, g_q_lo, nullptr);
    else if (z == 1) gemm_1024<0>(g_x_hi, g_x_lo, g_wk_hi, g_wk_lo, g_k_hi, g_k_lo, nullptr);
    else             gemm_1024<0>(g_x_hi, g_x_lo, g_wv_hi, g_wv_lo, g_v_hi, g_v_lo, nullptr);
}
__global__ __launch_bounds__(256, 2) void out_mma_kernel(float* __restrict__ out) {
    gemm_1024<1>(g_o_hi, g_o_lo, g_wo_hi, g_wo_lo, nullptr, nullptr, out);
}

// ---------------------------------------------------------------------------
// Tensor-core causal flash attention, 2-stage cp.async(.ca) pipeline.
// 64 q-rows/block, 4 warps x 16 rows.
// ---------------------------------------------------------------------------
#define AKS 72
#define AT_STG (64 * AKS * 2)                 // per array per stage: 9216 B
#define ATTN_SMEM (4 * 2 * AT_STG)            // 73728 B

__device__ __forceinline__ void attn_load_stage(
    int tid, int jb,
    const uint32_t* gkh, const uint32_t* gkl,
    const uint32_t* gvh, const uint32_t* gvl,
    uint32_t bKh, uint32_t bKl, uint32_t bVh, uint32_t bVl) {
    // 4 arrays x 64 rows x 8 chunks(16B) = 2048 chunks / 128 threads
#pragma unroll
    for (int i = 0; i < 16; i++) {
        int w = tid + i * 128;
        int arr = w >> 9, rem = w & 511;
        int r = rem >> 3, c = rem & 7;
        const uint32_t* g = (arr == 0 ? gkh : arr == 1 ? gkl : arr == 2 ? gvh : gvl)
                            + (size_t)(jb + r) * 512 + c * 4;
        uint32_t s = (arr == 0 ? bKh : arr == 1 ? bKl : arr == 2 ? bVh : bVl)
                     + r * (AKS * 2) + c * 16;
        cp_async16(s, g);
    }
}

__global__ __launch_bounds__(128, 2) void attn_mma_kernel() {
    extern __shared__ __align__(16) char dynsm[];
    const uint32_t bKh0 = smem_u32(dynsm);
    const uint32_t bKl0 = bKh0 + 2 * AT_STG;
    const uint32_t bVh0 = bKl0 + 2 * AT_STG;
    const uint32_t bVl0 = bVh0 + 2 * AT_STG;

    const int tid = threadIdx.x;
    const int lane = tid & 31, warp = tid >> 5;
    const int g = lane >> 2, t0 = lane & 3;
    const int h = blockIdx.y, b = blockIdx.z;
    const int qb = (int)(gridDim.x - 1 - blockIdx.x) * 64;   // heavy blocks first
    const int rowG = b * PL + qb + warp * 16;

    // Preload Q A-fragments (hi/lo), pre-scaled by 1/sqrt(Dh)=0.125 (exact)
    uint32_t qah[4][4], qal[4][4];
    {
        const uint32_t* qh32 = (const uint32_t*)g_q_hi;
        const uint32_t* ql32 = (const uint32_t*)g_q_lo;
        const __nv_bfloat162 sc2 = __float2bfloat162_rn(0.125f);
        size_t r0 = (size_t)(rowG + g) * 512, r1 = (size_t)(rowG + g + 8) * 512;
#pragma unroll
        for (int ks = 0; ks < 4; ks++) {
            int c = h * 32 + ks * 8 + t0;
            uint32_t v[8] = { qh32[r0 + c], qh32[r1 + c], qh32[r0 + c + 4], qh32[r1 + c + 4],
                              ql32[r0 + c], ql32[r1 + c], ql32[r0 + c + 4], ql32[r1 + c + 4] };
#pragma unroll
            for (int j = 0; j < 8; j++) {
                __nv_bfloat162 t = __hmul2(*reinterpret_cast<__nv_bfloat162*>(&v[j]), sc2);
                v[j] = *reinterpret_cast<uint32_t*>(&t);
            }
#pragma unroll
            for (int j = 0; j < 4; j++) { qah[ks][j] = v[j]; qal[ks][j] = v[j + 4]; }
        }
    }

    float oacc[8][4];
#pragma unroll
    for (int dn = 0; dn < 8; dn++)
#pragma unroll
        for (int j = 0; j < 4; j++) oacc[dn][j] = 0.f;
    float m0 = -1e30f, m1 = -1e30f, l0 = 0.f, l1 = 0.f;

    const int nA = lane & 7;
    const int sel8 = ((lane >> 3) & 1) * 8;
    const int sel16 = ((lane >> 4) & 1);
    const int qrow = qb + warp * 16 + g;

    const uint32_t* gkh = (const uint32_t*)g_k_hi + (size_t)(b * PL) * 512 + h * 32;
    const uint32_t* gkl = (const uint32_t*)g_k_lo + (size_t)(b * PL) * 512 + h * 32;
    const uint32_t* gvh = (const uint32_t*)g_v_hi + (size_t)(b * PL) * 512 + h * 32;
    const uint32_t* gvl = (const uint32_t*)g_v_lo + (size_t)(b * PL) * 512 + h * 32;

    const int ntiles = (qb >> 6) + 1;

    attn_load_stage(tid, 0, gkh, gkl, gvh, gvl, bKh0, bKl0, bVh0, bVl0);
    cp_commit();

    for (int t = 0; t < ntiles; t++) {
        const int jb = t * 64;
        const int s = t & 1;
        if (t + 1 < ntiles) {
            const int sn = s ^ 1;
            attn_load_stage(tid, jb + 64, gkh, gkl, gvh, gvl,
                            bKh0 + sn * AT_STG, bKl0 + sn * AT_STG,
                            bVh0 + sn * AT_STG, bVl0 + sn * AT_STG);
        }
        cp_commit();
        cp_wait<1>();
        __syncthreads();

        const uint32_t bKh = bKh0 + s * AT_STG, bKl = bKl0 + s * AT_STG;
        const uint32_t bVh = bVh0 + s * AT_STG, bVl = bVl0 + s * AT_STG;

        // ---- S = Q*K^T (16x64 per warp), 3-pass bf16 ----
        float sS[8][4];
#pragma unroll
        for (int ni = 0; ni < 8; ni++)
#pragma unroll
            for (int j = 0; j < 4; j++) sS[ni][j] = 0.f;

#pragma unroll
        for (int ks = 0; ks < 4; ks++) {
#pragma unroll
            for (int np = 0; np < 4; np++) {
                uint32_t off = (uint32_t)((((np * 2 + sel16) * 8 + nA) * AKS + ks * 16 + sel8) * 2);
                uint32_t kh0, kh1, kh2, kh3, kl0, kl1, kl2, kl3;
                ldsm_x4(kh0, kh1, kh2, kh3, bKh + off);
                ldsm_x4(kl0, kl1, kl2, kl3, bKl + off);
                mma_bf16(sS[np * 2],     qah[ks][0], qah[ks][1], qah[ks][2], qah[ks][3], kh0, kh1);
                mma_bf16(sS[np * 2],     qal[ks][0], qal[ks][1], qal[ks][2], qal[ks][3], kh0, kh1);
                mma_bf16(sS[np * 2],     qah[ks][0], qah[ks][1], qah[ks][2], qah[ks][3], kl0, kl1);
                mma_bf16(sS[np * 2 + 1], qah[ks][0], qah[ks][1], qah[ks][2], qah[ks][3], kh2, kh3);
                mma_bf16(sS[np * 2 + 1], qal[ks][0], qal[ks][1], qal[ks][2], qal[ks][3], kh2, kh3);
                mma_bf16(sS[np * 2 + 1], qah[ks][0], qah[ks][1], qah[ks][2], qah[ks][3], kl2, kl3);
            }
        }

        // Causal mask (diagonal tile only)
        if (jb == qb) {
            int r1 = qrow + 8;
#pragma unroll
            for (int ni = 0; ni < 8; ni++) {
                int k0 = jb + ni * 8 + 2 * t0;
                if (k0     > qrow) sS[ni][0] = -1e30f;
                if (k0 + 1 > qrow) sS[ni][1] = -1e30f;
                if (k0     > r1)   sS[ni][2] = -1e30f;
                if (k0 + 1 > r1)   sS[ni][3] = -1e30f;
            }
        }

        // ---- online softmax ----
        float cm0 = -1e30f, cm1 = -1e30f;
#pragma unroll
        for (int ni = 0; ni < 8; ni++) {
            cm0 = fmaxf(cm0, fmaxf(sS[ni][0], sS[ni][1]));
            cm1 = fmaxf(cm1, fmaxf(sS[ni][2], sS[ni][3]));
        }
        cm0 = fmaxf(cm0, __shfl_xor_sync(0xffffffffu, cm0, 1));
        cm0 = fmaxf(cm0, __shfl_xor_sync(0xffffffffu, cm0, 2));
        cm1 = fmaxf(cm1, __shfl_xor_sync(0xffffffffu, cm1, 1));
        cm1 = fmaxf(cm1, __shfl_xor_sync(0xffffffffu, cm1, 2));
        float nm0 = fmaxf(m0, cm0), nm1 = fmaxf(m1, cm1);
        float corr0 = __expf(m0 - nm0), corr1 = __expf(m1 - nm1);
        m0 = nm0; m1 = nm1;
        l0 *= corr0; l1 *= corr1;
#pragma unroll
        for (int dn = 0; dn < 8; dn++) {
            oacc[dn][0] *= corr0; oacc[dn][1] *= corr0;
            oacc[dn][2] *= corr1; oacc[dn][3] *= corr1;
        }
#pragma unroll
        for (int ni = 0; ni < 8; ni++) {
            sS[ni][0] = __expf(sS[ni][0] - nm0); sS[ni][1] = __expf(sS[ni][1] - nm0);
            sS[ni][2] = __expf(sS[ni][2] - nm1); sS[ni][3] = __expf(sS[ni][3] - nm1);
            l0 += sS[ni][0] + sS[ni][1];
            l1 += sS[ni][2] + sS[ni][3];
        }

        // P -> bf16 hi/lo A-fragments (C-frag layout == A-frag layout)
        uint32_t pah[4][4], pal[4][4];
#pragma unroll
        for (int ks2 = 0; ks2 < 4; ks2++) {
            split_pair(sS[2 * ks2][0],     sS[2 * ks2][1],     pah[ks2][0], pal[ks2][0]);
            split_pair(sS[2 * ks2][2],     sS[2 * ks2][3],     pah[ks2][1], pal[ks2][1]);
            split_pair(sS[2 * ks2 + 1][0], sS[2 * ks2 + 1][1], pah[ks2][2], pal[ks2][2]);
            split_pair(sS[2 * ks2 + 1][2], sS[2 * ks2 + 1][3], pah[ks2][3], pal[ks2][3]);
        }

        // ---- O += P*V, 3-pass bf16 ----
#pragma unroll
        for (int ks2 = 0; ks2 < 4; ks2++) {
#pragma unroll
            for (int dp = 0; dp < 4; dp++) {
                uint32_t off = (uint32_t)(((ks2 * 16 + nA + sel8) * AKS + (dp * 2 + sel16) * 8) * 2);
                uint32_t vh0, vh1, vh2, vh3, vl0, vl1, vl2, vl3;
                ldsm_x4t(vh0, vh1, vh2, vh3, bVh + off);
                ldsm_x4t(vl0, vl1, vl2, vl3, bVl + off);
                mma_bf16(oacc[dp * 2],     pah[ks2][0], pah[ks2][1], pah[ks2][2], pah[ks2][3], vh0, vh1);
                mma_bf16(oacc[dp * 2],     pal[ks2][0], pal[ks2][1], pal[ks2][2], pal[ks2][3], vh0, vh1);
                mma_bf16(oacc[dp * 2],     pah[ks2][0], pah[ks2][1], pah[ks2][2], pah[ks2][3], vl0, vl1);
                mma_bf16(oacc[dp * 2 + 1], pah[ks2][0], pah[ks2][1], pah[ks2][2], pah[ks2][3], vh2, vh3);
                mma_bf16(oacc[dp * 2 + 1], pal[ks2][0], pal[ks2][1], pal[ks2][2], pal[ks2][3], vh2, vh3);
                mma_bf16(oacc[dp * 2 + 1], pah[ks2][0], pah[ks2][1], pah[ks2][2], pah[ks2][3], vl2, vl3);
            }
        }
        __syncthreads();
    }

    // Reduce row sums across quad, normalize, write O as hi/lo
    l0 += __shfl_xor_sync(0xffffffffu, l0, 1);
    l0 += __shfl_xor_sync(0xffffffffu, l0, 2);
    l1 += __shfl_xor_sync(0xffffffffu, l1, 1);
    l1 += __shfl_xor_sync(0xffffffffu, l1, 2);
    float inv0 = 1.f / l0, inv1 = 1.f / l1;

    uint32_t* oh32 = (uint32_t*)g_o_hi;
    uint32_t* ol32 = (uint32_t*)g_o_lo;
    size_t r0 = (size_t)(rowG + g) * 512, r1 = (size_t)(rowG + g + 8) * 512;
#pragma unroll
    for (int dn = 0; dn < 8; dn++) {
        int c = h * 32 + dn * 4 + t0;
        uint32_t hh, ll;
        split_pair(oacc[dn][0] * inv0, oacc[dn][1] * inv0, hh, ll);
        oh32[r0 + c] = hh; ol32[r0 + c] = ll;
        split_pair(oacc[dn][2] * inv1, oacc[dn][3] * inv1, hh, ll);
        oh32[r1 + c] = hh; ol32[r1 + c] = ll;
    }
}

// ---------------------------------------------------------------------------
extern "C" void kernel_launch(void* const* d_in, const int* in_sizes, int n_in,
                              void* d_out, int out_size) {
    const float* x    = (const float*)d_in[0];
    const float* Wq   = (const float*)d_in[1];
    const float* Wk   = (const float*)d_in[2];
    const float* Wv   = (const float*)d_in[3];
    const float* Wout = (const float*)d_in[4];
    float* out = (float*)d_out;

    cudaFuncSetAttribute(qkv_mma_kernel, cudaFuncAttributeMaxDynamicSharedMemorySize, GEMM_SMEM);
    cudaFuncSetAttribute(out_mma_kernel, cudaFuncAttributeMaxDynamicSharedMemorySize, GEMM_SMEM);
    cudaFuncSetAttribute(attn_mma_kernel, cudaFuncAttributeMaxDynamicSharedMemorySize, ATTN_SMEM);

    dim3 splitGrid(128, 5);
    split_all_kernel<<<splitGrid, 256>>>(x, Wq, Wk, Wv, Wout);

    dim3 gemmGrid(8, 32, 3);
    qkv_mma_kernel<<<gemmGrid, 256, GEMM_SMEM>>>();

    dim3 attnGrid(32, PH, PB);
    attn_mma_kernel<<<attnGrid, 128, ATTN_SMEM>>>();

    dim3 outGrid(8, 32, 1);
    out_mma_kernel<<<outGrid, 256, GEMM_SMEM>>>(out);
}